// round 1
// baseline (speedup 1.0000x reference)
#include <cuda_runtime.h>
#include <cuda_bf16.h>
#include <math_constants.h>

// Problem constants
#define BSZ 4
#define SEQ 1024
#define TOK (BSZ * SEQ)          // 4096
#define DMODEL 2048
#define NHEADS 32
#define NKV 8
#define HDIM 64
#define GROUPS (NHEADS / NKV)     // 4
#define KVDIM (NKV * HDIM)        // 512
#define ATTN_SCALE 0.125f         // 64^-0.5

// ---------------- scratch (static device globals; no allocation) ----------
__device__ float g_Q[(size_t)TOK * DMODEL];     // [T, 32, 64]
__device__ float g_K[(size_t)TOK * KVDIM];      // [T, 8, 64]
__device__ float g_V[(size_t)TOK * KVDIM];      // [T, 8, 64]
__device__ float g_attn[(size_t)TOK * DMODEL];  // [T, 32, 64]

// ---------------- simple tiled fp32 GEMM: C[M,N] = A[M,K] @ B[K,N] --------
// M % 64 == 0, N % 64 == 0, K % 16 == 0 (holds for all four GEMMs here).
#define GBM 64
#define GBN 64
#define GBK 16

__global__ __launch_bounds__(256) void gemm_f32(
    const float* __restrict__ A, const float* __restrict__ B,
    float* __restrict__ C, int M, int N, int K)
{
    __shared__ float As[GBK][GBM];      // transposed A tile
    __shared__ float Bs[GBK][GBN];

    const int tid  = threadIdx.x;
    const int tx   = tid & 15;          // 0..15 -> 4 cols each
    const int ty   = tid >> 4;          // 0..15 -> 4 rows each
    const int brow = blockIdx.y * GBM;
    const int bcol = blockIdx.x * GBN;

    const int l  = tid * 4;
    const int ar = l >> 4, ac = l & 15;     // A tile coords (64x16)
    const int br = l >> 6, bc = l & 63;     // B tile coords (16x64)

    float acc[4][4];
#pragma unroll
    for (int i = 0; i < 4; i++)
#pragma unroll
        for (int j = 0; j < 4; j++) acc[i][j] = 0.f;

    for (int k0 = 0; k0 < K; k0 += GBK) {
        float4 av = *reinterpret_cast<const float4*>(
            A + (size_t)(brow + ar) * K + k0 + ac);
        As[ac + 0][ar] = av.x;
        As[ac + 1][ar] = av.y;
        As[ac + 2][ar] = av.z;
        As[ac + 3][ar] = av.w;

        float4 bv = *reinterpret_cast<const float4*>(
            B + (size_t)(k0 + br) * N + bcol + bc);
        *reinterpret_cast<float4*>(&Bs[br][bc]) = bv;

        __syncthreads();

#pragma unroll
        for (int kk = 0; kk < GBK; kk++) {
            float a[4], b[4];
#pragma unroll
            for (int i = 0; i < 4; i++) a[i] = As[kk][ty * 4 + i];
#pragma unroll
            for (int j = 0; j < 4; j++) b[j] = Bs[kk][tx * 4 + j];
#pragma unroll
            for (int i = 0; i < 4; i++)
#pragma unroll
                for (int j = 0; j < 4; j++)
                    acc[i][j] = fmaf(a[i], b[j], acc[i][j]);
        }
        __syncthreads();
    }

#pragma unroll
    for (int i = 0; i < 4; i++) {
        float4 v = make_float4(acc[i][0], acc[i][1], acc[i][2], acc[i][3]);
        *reinterpret_cast<float4*>(
            C + (size_t)(brow + ty * 4 + i) * N + bcol + tx * 4) = v;
    }
}

// ---------------- RoPE (in place) ------------------------------------------
// x: [T, H, 64]; cos/sin: [T, 32]. Rotate-half convention:
// out[i]    = x[i]   * c - x[i+32] * s
// out[i+32] = x[i+32]* c + x[i]    * s
__global__ void rope_kernel(float* __restrict__ x,
                            const float* __restrict__ cs,
                            const float* __restrict__ sn,
                            int H)
{
    int idx = blockIdx.x * blockDim.x + threadIdx.x;
    int total = TOK * H * 32;
    if (idx >= total) return;
    int i = idx & 31;
    int h = (idx >> 5) % H;
    int t = idx / (32 * H);
    float c = cs[t * 32 + i];
    float s = sn[t * 32 + i];
    float* p = x + (size_t)t * (H * HDIM) + h * HDIM;
    float x1 = p[i], x2 = p[i + 32];
    p[i]      = x1 * c - x2 * s;
    p[i + 32] = x2 * c + x1 * s;
}

// ---------------- causal GQA flash attention -------------------------------
// One block = 64 query rows of one (b, h). 64 threads, 1 row each.
// K/V tiles of 32 rows staged in shared memory; online softmax in registers.
#define FM 64
#define FN 32

__global__ __launch_bounds__(64) void flash_kernel(
    const float* __restrict__ Q, const float* __restrict__ K,
    const float* __restrict__ V, float* __restrict__ O)
{
    const int qt  = blockIdx.x;           // 0..15
    const int h   = blockIdx.y;           // 0..31
    const int b   = blockIdx.z;           // 0..3
    const int kvh = h / GROUPS;
    const int tid = threadIdx.x;          // 0..63

    const int qi = qt * FM + tid;         // row within sequence
    const int t  = b * SEQ + qi;          // token index

    __shared__ float Ks[FN][HDIM];
    __shared__ float Vs[FN][HDIM];

    float q[HDIM];
    const float* qp = Q + (size_t)t * DMODEL + h * HDIM;
#pragma unroll
    for (int d = 0; d < HDIM; d++) q[d] = qp[d] * ATTN_SCALE;

    float acc[HDIM];
#pragma unroll
    for (int d = 0; d < HDIM; d++) acc[d] = 0.f;
    float m = -CUDART_INF_F;
    float lsum = 0.f;

    const int kend = qt * FM + FM;        // exclusive upper bound of keys
    for (int kb = 0; kb < kend; kb += FN) {
        // stage K/V tile (coalesced; 32 floats per thread per tensor)
        for (int idx = tid; idx < FN * HDIM; idx += 64) {
            int j = idx >> 6;
            int d = idx & 63;
            int tk = b * SEQ + kb + j;
            Ks[j][d] = K[(size_t)tk * KVDIM + kvh * HDIM + d];
            Vs[j][d] = V[(size_t)tk * KVDIM + kvh * HDIM + d];
        }
        __syncthreads();

        float s[FN];
        float mb = -CUDART_INF_F;
#pragma unroll
        for (int j = 0; j < FN; j++) {
            // 4-way split accumulation for ILP
            float d0 = 0.f, d1 = 0.f, d2 = 0.f, d3 = 0.f;
#pragma unroll
            for (int d = 0; d < HDIM; d += 4) {
                d0 = fmaf(q[d + 0], Ks[j][d + 0], d0);
                d1 = fmaf(q[d + 1], Ks[j][d + 1], d1);
                d2 = fmaf(q[d + 2], Ks[j][d + 2], d2);
                d3 = fmaf(q[d + 3], Ks[j][d + 3], d3);
            }
            float dot = (d0 + d1) + (d2 + d3);
            s[j] = (kb + j <= qi) ? dot : -CUDART_INF_F;
            mb = fmaxf(mb, s[j]);
        }

        float mn = fmaxf(m, mb);
        float sf = __expf(m - mn);        // m=-inf first iter -> sf=0 (mn finite)
        lsum *= sf;
#pragma unroll
        for (int d = 0; d < HDIM; d++) acc[d] *= sf;

#pragma unroll
        for (int j = 0; j < FN; j++) {
            float p = __expf(s[j] - mn);  // masked -> exp(-inf)=0
            lsum += p;
#pragma unroll
            for (int d = 0; d < HDIM; d++)
                acc[d] = fmaf(p, Vs[j][d], acc[d]);
        }
        m = mn;
        __syncthreads();
    }

    float inv = 1.0f / lsum;
    float* op = O + (size_t)t * DMODEL + h * HDIM;
#pragma unroll
    for (int d = 0; d < HDIM; d++) op[d] = acc[d] * inv;
}

// ---------------- launch ----------------------------------------------------
extern "C" void kernel_launch(void* const* d_in, const int* in_sizes, int n_in,
                              void* d_out, int out_size)
{
    const float* hidden = (const float*)d_in[0];   // [T, 2048]
    const float* cs     = (const float*)d_in[1];   // [T, 32]
    const float* sn     = (const float*)d_in[2];   // [T, 32]
    const float* Wq     = (const float*)d_in[3];   // [2048, 2048]
    const float* Wk     = (const float*)d_in[4];   // [2048, 512]
    const float* Wv     = (const float*)d_in[5];   // [2048, 512]
    const float* Wo     = (const float*)d_in[6];   // [2048, 2048]
    float* out          = (float*)d_out;           // [T, 2048]

    float* Q  = nullptr; cudaGetSymbolAddress((void**)&Q,  g_Q);
    float* Kp = nullptr; cudaGetSymbolAddress((void**)&Kp, g_K);
    float* Vp = nullptr; cudaGetSymbolAddress((void**)&Vp, g_V);
    float* At = nullptr; cudaGetSymbolAddress((void**)&At, g_attn);

    dim3 gq(DMODEL / GBN, TOK / GBM);
    dim3 gkv(KVDIM / GBN, TOK / GBM);

    // Projections
    gemm_f32<<<gq, 256>>>(hidden, Wq, Q, TOK, DMODEL, DMODEL);
    gemm_f32<<<gkv, 256>>>(hidden, Wk, Kp, TOK, KVDIM, DMODEL);
    gemm_f32<<<gkv, 256>>>(hidden, Wv, Vp, TOK, KVDIM, DMODEL);

    // RoPE on q and k
    {
        int totq = TOK * NHEADS * 32;
        rope_kernel<<<(totq + 255) / 256, 256>>>(Q, cs, sn, NHEADS);
        int totk = TOK * NKV * 32;
        rope_kernel<<<(totk + 255) / 256, 256>>>(Kp, cs, sn, NKV);
    }

    // Attention
    {
        dim3 grid(SEQ / FM, NHEADS, BSZ);
        flash_kernel<<<grid, 64>>>(Q, Kp, Vp, At);
    }

    // Output projection
    gemm_f32<<<gq, 256>>>(At, Wo, out, TOK, DMODEL, DMODEL);
}

// round 2
// speedup vs baseline: 1.0032x; 1.0032x over previous
#include <cuda_runtime.h>
#include <cuda_bf16.h>
#include <math_constants.h>

// Problem constants
#define BSZ 4
#define SEQ 1024
#define TOK (BSZ * SEQ)          // 4096
#define DMODEL 2048
#define NHEADS 32
#define NKV 8
#define HDIM 64
#define GROUPS (NHEADS / NKV)     // 4
#define KVDIM (NKV * HDIM)        // 512
#define ATTN_SCALE 0.125f         // 64^-0.5

// ---------------- scratch (static device globals; no allocation) ----------
__device__ float g_Q[(size_t)TOK * DMODEL];     // [T, 32, 64]
__device__ float g_K[(size_t)TOK * KVDIM];      // [T, 8, 64]
__device__ float g_V[(size_t)TOK * KVDIM];      // [T, 8, 64]
__device__ float g_attn[(size_t)TOK * DMODEL];  // [T, 32, 64]

// ---------------- simple tiled fp32 GEMM: C[M,N] = A[M,K] @ B[K,N] --------
// M % 64 == 0, N % 64 == 0, K % 16 == 0 (holds for all four GEMMs here).
#define GBM 64
#define GBN 64
#define GBK 16

__global__ __launch_bounds__(256) void gemm_f32(
    const float* __restrict__ A, const float* __restrict__ B,
    float* __restrict__ C, int M, int N, int K)
{
    __shared__ float As[GBK][GBM];      // transposed A tile
    __shared__ float Bs[GBK][GBN];

    const int tid  = threadIdx.x;
    const int tx   = tid & 15;          // 0..15 -> 4 cols each
    const int ty   = tid >> 4;          // 0..15 -> 4 rows each
    const int brow = blockIdx.y * GBM;
    const int bcol = blockIdx.x * GBN;

    const int l  = tid * 4;
    const int ar = l >> 4, ac = l & 15;     // A tile coords (64x16)
    const int br = l >> 6, bc = l & 63;     // B tile coords (16x64)

    float acc[4][4];
#pragma unroll
    for (int i = 0; i < 4; i++)
#pragma unroll
        for (int j = 0; j < 4; j++) acc[i][j] = 0.f;

    for (int k0 = 0; k0 < K; k0 += GBK) {
        float4 av = *reinterpret_cast<const float4*>(
            A + (size_t)(brow + ar) * K + k0 + ac);
        As[ac + 0][ar] = av.x;
        As[ac + 1][ar] = av.y;
        As[ac + 2][ar] = av.z;
        As[ac + 3][ar] = av.w;

        float4 bv = *reinterpret_cast<const float4*>(
            B + (size_t)(k0 + br) * N + bcol + bc);
        *reinterpret_cast<float4*>(&Bs[br][bc]) = bv;

        __syncthreads();

#pragma unroll
        for (int kk = 0; kk < GBK; kk++) {
            float a[4], b[4];
#pragma unroll
            for (int i = 0; i < 4; i++) a[i] = As[kk][ty * 4 + i];
#pragma unroll
            for (int j = 0; j < 4; j++) b[j] = Bs[kk][tx * 4 + j];
#pragma unroll
            for (int i = 0; i < 4; i++)
#pragma unroll
                for (int j = 0; j < 4; j++)
                    acc[i][j] = fmaf(a[i], b[j], acc[i][j]);
        }
        __syncthreads();
    }

#pragma unroll
    for (int i = 0; i < 4; i++) {
        float4 v = make_float4(acc[i][0], acc[i][1], acc[i][2], acc[i][3]);
        *reinterpret_cast<float4*>(
            C + (size_t)(brow + ty * 4 + i) * N + bcol + tx * 4) = v;
    }
}

// ---------------- RoPE (in place) ------------------------------------------
// x: [T, H, 64]; cos/sin: [T, 32]. Rotate-half convention:
// out[i]    = x[i]   * c - x[i+32] * s
// out[i+32] = x[i+32]* c + x[i]    * s
__global__ void rope_kernel(float* __restrict__ x,
                            const float* __restrict__ cs,
                            const float* __restrict__ sn,
                            int H)
{
    int idx = blockIdx.x * blockDim.x + threadIdx.x;
    int total = TOK * H * 32;
    if (idx >= total) return;
    int i = idx & 31;
    int h = (idx >> 5) % H;
    int t = idx / (32 * H);
    float c = cs[t * 32 + i];
    float s = sn[t * 32 + i];
    float* p = x + (size_t)t * (H * HDIM) + h * HDIM;
    float x1 = p[i], x2 = p[i + 32];
    p[i]      = x1 * c - x2 * s;
    p[i + 32] = x2 * c + x1 * s;
}

// ---------------- causal GQA flash attention -------------------------------
// One block = 64 query rows of one (b, h). 64 threads, 1 row each.
// K/V tiles of 32 rows staged in shared memory; online softmax in registers.
#define FM 64
#define FN 32

__global__ __launch_bounds__(64) void flash_kernel(
    const float* __restrict__ Q, const float* __restrict__ K,
    const float* __restrict__ V, float* __restrict__ O)
{
    const int qt  = blockIdx.x;           // 0..15
    const int h   = blockIdx.y;           // 0..31
    const int b   = blockIdx.z;           // 0..3
    const int kvh = h / GROUPS;
    const int tid = threadIdx.x;          // 0..63

    const int qi = qt * FM + tid;         // row within sequence
    const int t  = b * SEQ + qi;          // token index

    __shared__ float Ks[FN][HDIM];
    __shared__ float Vs[FN][HDIM];

    float q[HDIM];
    const float* qp = Q + (size_t)t * DMODEL + h * HDIM;
#pragma unroll
    for (int d = 0; d < HDIM; d++) q[d] = qp[d] * ATTN_SCALE;

    float acc[HDIM];
#pragma unroll
    for (int d = 0; d < HDIM; d++) acc[d] = 0.f;
    float m = -CUDART_INF_F;
    float lsum = 0.f;

    const int kend = qt * FM + FM;        // exclusive upper bound of keys
    for (int kb = 0; kb < kend; kb += FN) {
        // stage K/V tile (coalesced; 32 floats per thread per tensor)
        for (int idx = tid; idx < FN * HDIM; idx += 64) {
            int j = idx >> 6;
            int d = idx & 63;
            int tk = b * SEQ + kb + j;
            Ks[j][d] = K[(size_t)tk * KVDIM + kvh * HDIM + d];
            Vs[j][d] = V[(size_t)tk * KVDIM + kvh * HDIM + d];
        }
        __syncthreads();

        float s[FN];
        float mb = -CUDART_INF_F;
#pragma unroll
        for (int j = 0; j < FN; j++) {
            // 4-way split accumulation for ILP
            float d0 = 0.f, d1 = 0.f, d2 = 0.f, d3 = 0.f;
#pragma unroll
            for (int d = 0; d < HDIM; d += 4) {
                d0 = fmaf(q[d + 0], Ks[j][d + 0], d0);
                d1 = fmaf(q[d + 1], Ks[j][d + 1], d1);
                d2 = fmaf(q[d + 2], Ks[j][d + 2], d2);
                d3 = fmaf(q[d + 3], Ks[j][d + 3], d3);
            }
            float dot = (d0 + d1) + (d2 + d3);
            s[j] = (kb + j <= qi) ? dot : -CUDART_INF_F;
            mb = fmaxf(mb, s[j]);
        }

        float mn = fmaxf(m, mb);
        float sf = __expf(m - mn);        // m=-inf first iter -> sf=0 (mn finite)
        lsum *= sf;
#pragma unroll
        for (int d = 0; d < HDIM; d++) acc[d] *= sf;

#pragma unroll
        for (int j = 0; j < FN; j++) {
            float p = __expf(s[j] - mn);  // masked -> exp(-inf)=0
            lsum += p;
#pragma unroll
            for (int d = 0; d < HDIM; d++)
                acc[d] = fmaf(p, Vs[j][d], acc[d]);
        }
        m = mn;
        __syncthreads();
    }

    float inv = 1.0f / lsum;
    float* op = O + (size_t)t * DMODEL + h * HDIM;
#pragma unroll
    for (int d = 0; d < HDIM; d++) op[d] = acc[d] * inv;
}

// ---------------- launch ----------------------------------------------------
extern "C" void kernel_launch(void* const* d_in, const int* in_sizes, int n_in,
                              void* d_out, int out_size)
{
    const float* hidden = (const float*)d_in[0];   // [T, 2048]
    const float* cs     = (const float*)d_in[1];   // [T, 32]
    const float* sn     = (const float*)d_in[2];   // [T, 32]
    const float* Wq     = (const float*)d_in[3];   // [2048, 2048]
    const float* Wk     = (const float*)d_in[4];   // [2048, 512]
    const float* Wv     = (const float*)d_in[5];   // [2048, 512]
    const float* Wo     = (const float*)d_in[6];   // [2048, 2048]
    float* out          = (float*)d_out;           // [T, 2048]

    float* Q  = nullptr; cudaGetSymbolAddress((void**)&Q,  g_Q);
    float* Kp = nullptr; cudaGetSymbolAddress((void**)&Kp, g_K);
    float* Vp = nullptr; cudaGetSymbolAddress((void**)&Vp, g_V);
    float* At = nullptr; cudaGetSymbolAddress((void**)&At, g_attn);

    dim3 gq(DMODEL / GBN, TOK / GBM);
    dim3 gkv(KVDIM / GBN, TOK / GBM);

    // Projections
    gemm_f32<<<gq, 256>>>(hidden, Wq, Q, TOK, DMODEL, DMODEL);
    gemm_f32<<<gkv, 256>>>(hidden, Wk, Kp, TOK, KVDIM, DMODEL);
    gemm_f32<<<gkv, 256>>>(hidden, Wv, Vp, TOK, KVDIM, DMODEL);

    // RoPE on q and k
    {
        int totq = TOK * NHEADS * 32;
        rope_kernel<<<(totq + 255) / 256, 256>>>(Q, cs, sn, NHEADS);
        int totk = TOK * NKV * 32;
        rope_kernel<<<(totk + 255) / 256, 256>>>(Kp, cs, sn, NKV);
    }

    // Attention
    {
        dim3 grid(SEQ / FM, NHEADS, BSZ);
        flash_kernel<<<grid, 64>>>(Q, Kp, Vp, At);
    }

    // Output projection
    gemm_f32<<<gq, 256>>>(At, Wo, out, TOK, DMODEL, DMODEL);
}